// round 15
// baseline (speedup 1.0000x reference)
#include <cuda_runtime.h>
#include <cstdint>
#include <math.h>

// Problem constants
#define BATCH 4
#define MPAR  64
#define N2  512
#define N1  2048
#define N0  8192
#define C2  256
#define C1  128
#define C0  64

#define NT1 (BATCH * N1)          // 8192
#define NT0 (BATCH * N0)          // 32768
#define KD1 (C2 + C1)             // 384
#define H1  256
#define O1  128
#define KD2 (O1 + C0)             // 192
#define H2  128
#define O2  64

// packed fragment counts: (K/8) * (N/8) * 32 float4 each
#define S1A ((KD1 / 8) * (H1 / 8) * 32)   // 49152
#define S1B ((H1 / 8) * (O1 / 8) * 32)    // 16384
#define S2A ((KD2 / 8) * (H2 / 8) * 32)   // 12288
#define S2B ((H2 / 8) * (O2 / 8) * 32)    // 4096

// -------- scratch (referenced ONLY from device code) --------
__device__ float  g_x1   [NT1 * O1];
__device__ int    g_idx1 [NT1 * 3];
__device__ float  g_w1   [NT1 * 3];
__device__ int    g_idx2 [NT0 * 3];
__device__ float  g_w2   [NT0 * 3];
__device__ float  g_p0   [BATCH * O1];
__device__ float  g_p1   [BATCH * O2];
// weights pre-packed into mma B-fragment order (big/small float4 per lane)
__device__ float4 g_Wa1p[S1A];
__device__ float4 g_Wb1p[S1B];
__device__ float4 g_Wa2p[S2A];
__device__ float4 g_Wb2p[S2B];

__device__ __forceinline__ float ftanh(float x) {
    float e = __expf(2.0f * x);
    return 1.0f - __fdividef(2.0f, e + 1.0f);
}

__device__ __forceinline__ uint32_t f2tf(float x) {
    uint32_t u;
    asm("cvt.rna.tf32.f32 %0, %1;" : "=r"(u) : "f"(x));
    return u;
}

__device__ __forceinline__ float2 split_w(float x) {
    uint32_t bu = f2tf(x);
    float bf = __uint_as_float(bu);
    float s  = x - bf;
    return make_float2(bf, __uint_as_float(f2tf(s)));
}

__device__ __forceinline__ void mma8(float* c,
                                     uint32_t a0, uint32_t a1, uint32_t a2, uint32_t a3,
                                     uint32_t b0, uint32_t b1) {
    asm volatile(
        "mma.sync.aligned.m16n8k8.row.col.f32.tf32.tf32.f32 "
        "{%0,%1,%2,%3},{%4,%5,%6,%7},{%8,%9},{%0,%1,%2,%3};"
        : "+f"(c[0]), "+f"(c[1]), "+f"(c[2]), "+f"(c[3])
        : "r"(a0), "r"(a1), "r"(a2), "r"(a3), "r"(b0), "r"(b1));
}

__device__ __forceinline__ void pack_one(const float* __restrict__ W, int ncols, int ntf,
                                         int id, float4* __restrict__ dst)
{
    int lane = id & 31;
    int rem  = id >> 5;
    int nt   = rem % ntf;
    int ksg  = rem / ntf;
    int g = lane >> 2, tig = lane & 3;
    int n  = nt * 8 + g;
    int k0 = ksg * 8 + tig;
    float2 s0 = split_w(W[k0 * ncols + n]);
    float2 s1 = split_w(W[(k0 + 4) * ncols + n]);
    dst[id] = make_float4(s0.x, s0.y, s1.x, s1.y);
}

// -------- prep: weight fragment packing + par branch (one launch) --------
__global__ void prep_kernel(const float* __restrict__ W0a, const float* __restrict__ W0b,
                            const float* __restrict__ W1a, const float* __restrict__ W1b,
                            const float* __restrict__ par,
                            const float* __restrict__ Wp0, const float* __restrict__ bp0,
                            const float* __restrict__ Wp1, const float* __restrict__ bp1)
{
    int i = blockIdx.x * 256 + threadIdx.x;
    if (i < S1A)                         pack_one(W0a, H1, H1 / 8, i, g_Wa1p);
    else if (i < S1A + S1B)              pack_one(W0b, O1, O1 / 8, i - S1A, g_Wb1p);
    else if (i < S1A + S1B + S2A)        pack_one(W1a, H2, H2 / 8, i - S1A - S1B, g_Wa2p);
    else if (i < S1A + S1B + S2A + S2B)  pack_one(W1b, O2, O2 / 8, i - S1A - S1B - S2A, g_Wb2p);

    if (blockIdx.x == 0 && threadIdx.x < 128) {
        int j = threadIdx.x;
        #pragma unroll
        for (int b = 0; b < BATCH; b++) {
            float a0 = 0.0f;
            #pragma unroll 8
            for (int m = 0; m < MPAR; m++)
                a0 = fmaf(par[b * MPAR + m], Wp0[m * O1 + j], a0);
            g_p0[b * O1 + j] = ftanh(a0 + bp0[j]);
            if (j < O2) {
                float a1 = 0.0f;
                #pragma unroll 8
                for (int m = 0; m < MPAR; m++)
                    a1 = fmaf(par[b * MPAR + m], Wp1[m * O2 + j], a1);
                g_p1[b * O2 + j] = ftanh(a1 + bp1[j]);
            }
        }
    }
}

// -------- KNN (k=3), 4-way source split, 4-wide min-screen --------
template<int LAYER>
__global__ __launch_bounds__(512) void knn_kernel(const float* __restrict__ pos_src,
                                                  const float* __restrict__ pos_tgt)
{
    constexpr int NS  = (LAYER == 1) ? N2 : N1;
    constexpr int TPB = (LAYER == 1) ? N1 : N0;
    constexpr int TPT = 128;
    constexpr int SC  = NS / 4;

    __shared__ float4 sp[NS];
    __shared__ float  sd[3][512];
    __shared__ int    si[3][512];

    int* __restrict__ idx_out  = (LAYER == 1) ? g_idx1 : g_idx2;
    float* __restrict__ w_out  = (LAYER == 1) ? g_w1   : g_w2;

    const int bpb = TPB / TPT;
    const int b   = blockIdx.x / bpb;
    const int t0  = (blockIdx.x % bpb) * TPT;
    const int tid = threadIdx.x;
    const int lt    = tid & (TPT - 1);
    const int chunk = tid >> 7;

    const float* ps = pos_src + (size_t)b * NS * 3;
    for (int i = tid; i < NS; i += 512) {
        float sx = ps[i * 3 + 0], sy = ps[i * 3 + 1], sz = ps[i * 3 + 2];
        sp[i] = make_float4(sx, sy, sz, fmaf(sx, sx, fmaf(sy, sy, sz * sz)));
    }
    __syncthreads();

    const int gt = b * TPB + t0 + lt;
    const float px = pos_tgt[gt * 3 + 0];
    const float py = pos_tgt[gt * 3 + 1];
    const float pz = pos_tgt[gt * 3 + 2];
    const float nx = -2.0f * px, ny = -2.0f * py, nz = -2.0f * pz;

    float d0 = 3.4e38f, d1 = 3.4e38f, d2 = 3.4e38f;
    int   i0 = 0, i1 = 0, i2 = 0;

    auto insert3 = [&](float d, int s) {
        if (d < d2) {
            if (d < d1) {
                d2 = d1; i2 = i1;
                if (d < d0) { d1 = d0; i1 = i0; d0 = d; i0 = s; }
                else        { d1 = d;  i1 = s; }
            } else { d2 = d; i2 = s; }
        }
    };

    const int sbeg = chunk * SC;
    #pragma unroll 2
    for (int s = sbeg; s < sbeg + SC; s += 4) {
        float4 va = sp[s + 0], vb = sp[s + 1], vc = sp[s + 2], vd = sp[s + 3];
        float da = fmaf(nx, va.x, fmaf(ny, va.y, fmaf(nz, va.z, va.w)));
        float db = fmaf(nx, vb.x, fmaf(ny, vb.y, fmaf(nz, vb.z, vb.w)));
        float dc = fmaf(nx, vc.x, fmaf(ny, vc.y, fmaf(nz, vc.z, vc.w)));
        float dd = fmaf(nx, vd.x, fmaf(ny, vd.y, fmaf(nz, vd.z, vd.w)));
        if (fminf(fminf(da, db), fminf(dc, dd)) < d2) {
            insert3(da, s);
            insert3(db, s + 1);
            insert3(dc, s + 2);
            insert3(dd, s + 3);
        }
    }

    sd[0][tid] = d0; sd[1][tid] = d1; sd[2][tid] = d2;
    si[0][tid] = i0; si[1][tid] = i1; si[2][tid] = i2;
    __syncthreads();

    if (tid < TPT) {
        #pragma unroll
        for (int c = 1; c < 4; c++) {
            #pragma unroll
            for (int j = 0; j < 3; j++)
                insert3(sd[j][c * TPT + lt], si[j][c * TPT + lt]);
        }

        float4 v0 = sp[i0], v1 = sp[i1], v2 = sp[i2];
        float dx, dy, dz;
        dx = px - v0.x; dy = py - v0.y; dz = pz - v0.z;
        float e0 = fmaf(dx, dx, fmaf(dy, dy, dz * dz));
        dx = px - v1.x; dy = py - v1.y; dz = pz - v1.z;
        float e1 = fmaf(dx, dx, fmaf(dy, dy, dz * dz));
        dx = px - v2.x; dy = py - v2.y; dz = pz - v2.z;
        float e2 = fmaf(dx, dx, fmaf(dy, dy, dz * dz));

        const int base = b * NS;
        idx_out[gt * 3 + 0] = base + i0;
        idx_out[gt * 3 + 1] = base + i1;
        idx_out[gt * 3 + 2] = base + i2;
        w_out[gt * 3 + 0] = __fdividef(1.0f, fmaxf(e0, 1e-16f));
        w_out[gt * 3 + 1] = __fdividef(1.0f, fmaxf(e1, 1e-16f));
        w_out[gt * 3 + 2] = __fdividef(1.0f, fmaxf(e2, 1e-16f));
    }
}

// -------- fused interp + concat + 2-layer MLP (3xTF32, fragment-packed B) ----
// 512 threads / 16 warps: 2 row-warp groups (16 rows) x 8 col-warp groups.
// R = 32 rows per block. Same tiles as the 256-thread version but double the
// warps per SM for latency hiding (occupancy was the binder).
template<int LAYER>
__global__ __launch_bounds__(512, 2) void mlp_kernel(
    const float* __restrict__ ba, const float* __restrict__ bb,
    const float* __restrict__ xsrc_arg, const float* __restrict__ xskip,
    const float* __restrict__ pos_tail, const int* __restrict__ bat_tail,
    int do_tail, float* __restrict__ out_arg)
{
    constexpr int KD  = (LAYER == 1) ? KD1 : KD2;   // 384 / 192
    constexpr int H   = (LAYER == 1) ? H1  : H2;    // 256 / 128
    constexpr int O   = (LAYER == 1) ? O1  : O2;    // 128 / 64
    constexpr int C   = (LAYER == 1) ? C2  : O1;    // interp width
    constexpr int CS  = KD - C;                     // skip width
    constexpr bool PLAIN = (LAYER == 2);
    constexpr int RPB = (LAYER == 1) ? N1 : N0;
    constexpr int XP  = KD + 4;                     // padded xs stride (floats)
    constexpr int HP  = H + 4;                      // padded hs stride (floats)
    constexpr int BK  = 16;                         // k per staged tile (2 ks)
    constexpr int KT1 = KD / BK;
    constexpr int KT2 = H / BK;
    constexpr int NTF1 = H / 8;                     // fragment cols, phase 1
    constexpr int NTF2 = O / 8;                     // fragment cols, phase 2
    constexpr int NTA = H / 64;                     // n-tiles/warp phase1 (4/2)
    constexpr int NTB = O / 64;                     // n-tiles/warp phase2 (2/1)
    constexpr int PF1 = 2 * NTF1 * 32 / 512;        // float4/thread per tile (4/2)
    constexpr int PF2 = 2 * NTF2 * 32 / 512;        // (2/1)

    extern __shared__ char smem_raw[];
    float*  xs  = (float*)smem_raw;                 // 32*XP floats; aliased as hs
    float*  hs  = xs;
    float4* ws4 = (float4*)(smem_raw + 32 * XP * 4);

    const float4* __restrict__ Wap = (LAYER == 1) ? g_Wa1p : g_Wa2p;
    const float4* __restrict__ Wbp = (LAYER == 1) ? g_Wb1p : g_Wb2p;
    const float*  __restrict__ xsrc = (LAYER == 1) ? xsrc_arg : g_x1;
    const int*    __restrict__ idx  = (LAYER == 1) ? g_idx1 : g_idx2;
    const float*  __restrict__ wgt  = (LAYER == 1) ? g_w1   : g_w2;
    const float*  __restrict__ p    = (LAYER == 1) ? g_p0 : g_p1;
    float*        __restrict__ outp = (LAYER == 1) ? g_x1 : out_arg;

    const int tid  = threadIdx.x;
    const int lane = tid & 31;
    const int w    = tid >> 5;           // 0..15
    const int rw   = w >> 3;             // 0..1 row-warp group
    const int cw   = w & 7;              // 0..7 col-warp group
    const int g    = lane >> 2;          // 0..7 mma group
    const int tig  = lane & 3;           // 0..3 thread-in-group
    const int m0   = rw * 16;
    const int row0 = blockIdx.x * 32;

    // ---- tail copy (LAYER 2 only; grid 1024 x 128 = 131072 elems) ----
    if (LAYER == 2 && do_tail && tid < 128) {
        const int i = blockIdx.x * 128 + tid;
        const int NP = NT0 * 3;
        float v = (i < NP) ? pos_tail[i] : (float)bat_tail[i - NP];
        out_arg[(size_t)NT0 * O2 + i] = v;
    }

    // ---- staging: interpolate + concat into xs (warp per row) ----
    for (int rr = w; rr < 32; rr += 16) {
        const int t = row0 + rr;
        const int j0 = idx[t * 3 + 0], j1 = idx[t * 3 + 1], j2 = idx[t * 3 + 2];
        float w0 = wgt[t * 3 + 0], w1 = wgt[t * 3 + 1], w2 = wgt[t * 3 + 2];
        const float inv = __fdividef(1.0f, w0 + w1 + w2);
        w0 *= inv; w1 *= inv; w2 *= inv;

        const float4* r0 = reinterpret_cast<const float4*>(xsrc + (size_t)j0 * C);
        const float4* r1 = reinterpret_cast<const float4*>(xsrc + (size_t)j1 * C);
        const float4* r2 = reinterpret_cast<const float4*>(xsrc + (size_t)j2 * C);
        float4* xrow4 = reinterpret_cast<float4*>(xs + rr * XP);

        #pragma unroll
        for (int c = lane; c < C / 4; c += 32) {
            float4 a = r0[c], bq = r1[c], cq = r2[c];
            float4 o;
            o.x = fmaf(w0, a.x, fmaf(w1, bq.x, w2 * cq.x));
            o.y = fmaf(w0, a.y, fmaf(w1, bq.y, w2 * cq.y));
            o.z = fmaf(w0, a.z, fmaf(w1, bq.z, w2 * cq.z));
            o.w = fmaf(w0, a.w, fmaf(w1, bq.w, w2 * cq.w));
            xrow4[c] = o;
        }
        const float4* sk = reinterpret_cast<const float4*>(xskip + (size_t)t * CS);
        #pragma unroll
        for (int c = lane; c < CS / 4; c += 32)
            xrow4[C / 4 + c] = sk[c];
    }

    // preload Wa tile 0 (packed fragments, linear)
    float4 wr[PF1];
    #pragma unroll
    for (int j = 0; j < PF1; j++) wr[j] = Wap[j * 512 + tid];

    // ---- phase 1: X(32xKD) @ Wa(KDxH) -> tanh -> hs ----
    float acc[NTA][4];
    #pragma unroll
    for (int n = 0; n < NTA; n++)
        #pragma unroll
        for (int q = 0; q < 4; q++) acc[n][q] = 0.0f;

    for (int t = 0; t < KT1; t++) {
        #pragma unroll
        for (int j = 0; j < PF1; j++) ws4[j * 512 + tid] = wr[j];
        __syncthreads();
        if (t + 1 < KT1) {
            #pragma unroll
            for (int j = 0; j < PF1; j++)
                wr[j] = Wap[(t + 1) * (PF1 * 512) + j * 512 + tid];
        }
        #pragma unroll
        for (int ks = 0; ks < 2; ks++) {
            const int kk = t * BK + ks * 8;
            float a0f = xs[(m0 + g) * XP + kk + tig];
            float a1f = xs[(m0 + g + 8) * XP + kk + tig];
            float a2f = xs[(m0 + g) * XP + kk + tig + 4];
            float a3f = xs[(m0 + g + 8) * XP + kk + tig + 4];
            uint32_t a0b = f2tf(a0f), a1b = f2tf(a1f), a2b = f2tf(a2f), a3b = f2tf(a3f);
            uint32_t a0s = f2tf(a0f - __uint_as_float(a0b));
            uint32_t a1s = f2tf(a1f - __uint_as_float(a1b));
            uint32_t a2s = f2tf(a2f - __uint_as_float(a2b));
            uint32_t a3s = f2tf(a3f - __uint_as_float(a3b));
            #pragma unroll
            for (int nt = 0; nt < NTA; nt++) {
                float4 f = ws4[(ks * NTF1 + cw * NTA + nt) * 32 + lane];
                uint32_t b0b = __float_as_uint(f.x), b0s = __float_as_uint(f.y);
                uint32_t b1b = __float_as_uint(f.z), b1s = __float_as_uint(f.w);
                mma8(acc[nt], a0b, a1b, a2b, a3b, b0b, b1b);
                mma8(acc[nt], a0b, a1b, a2b, a3b, b0s, b1s);
                mma8(acc[nt], a0s, a1s, a2s, a3s, b0b, b1b);
            }
        }
        __syncthreads();
    }

    // preload Wb tile 0
    float4 wr2[PF2];
    #pragma unroll
    for (int j = 0; j < PF2; j++) wr2[j] = Wbp[j * 512 + tid];

    // tanh epilogue -> hs (aliases xs; all xs reads complete after final sync)
    #pragma unroll
    for (int nt = 0; nt < NTA; nt++) {
        const int col = cw * (H / 8) + nt * 8 + tig * 2;
        float2 bv = *reinterpret_cast<const float2*>(ba + col);
        float2 lo = make_float2(ftanh(acc[nt][0] + bv.x), ftanh(acc[nt][1] + bv.y));
        float2 hi = make_float2(ftanh(acc[nt][2] + bv.x), ftanh(acc[nt][3] + bv.y));
        *reinterpret_cast<float2*>(hs + (m0 + g) * HP + col)     = lo;
        *reinterpret_cast<float2*>(hs + (m0 + g + 8) * HP + col) = hi;
    }

    // ---- phase 2: hs(32xH) @ Wb(HxO) ----
    float acc2[NTB][4];
    #pragma unroll
    for (int n = 0; n < NTB; n++)
        #pragma unroll
        for (int q = 0; q < 4; q++) acc2[n][q] = 0.0f;

    for (int t = 0; t < KT2; t++) {
        #pragma unroll
        for (int j = 0; j < PF2; j++) ws4[j * 512 + tid] = wr2[j];
        __syncthreads();   // also orders hs stores before hs reads (t==0)
        if (t + 1 < KT2) {
            #pragma unroll
            for (int j = 0; j < PF2; j++)
                wr2[j] = Wbp[(t + 1) * (PF2 * 512) + j * 512 + tid];
        }
        #pragma unroll
        for (int ks = 0; ks < 2; ks++) {
            const int kk = t * BK + ks * 8;
            float a0f = hs[(m0 + g) * HP + kk + tig];
            float a1f = hs[(m0 + g + 8) * HP + kk + tig];
            float a2f = hs[(m0 + g) * HP + kk + tig + 4];
            float a3f = hs[(m0 + g + 8) * HP + kk + tig + 4];
            uint32_t a0b = f2tf(a0f), a1b = f2tf(a1f), a2b = f2tf(a2f), a3b = f2tf(a3f);
            uint32_t a0s = f2tf(a0f - __uint_as_float(a0b));
            uint32_t a1s = f2tf(a1f - __uint_as_float(a1b));
            uint32_t a2s = f2tf(a2f - __uint_as_float(a2b));
            uint32_t a3s = f2tf(a3f - __uint_as_float(a3b));
            #pragma unroll
            for (int nt = 0; nt < NTB; nt++) {
                float4 f = ws4[(ks * NTF2 + cw * NTB + nt) * 32 + lane];
                uint32_t b0b = __float_as_uint(f.x), b0s = __float_as_uint(f.y);
                uint32_t b1b = __float_as_uint(f.z), b1s = __float_as_uint(f.w);
                mma8(acc2[nt], a0b, a1b, a2b, a3b, b0b, b1b);
                mma8(acc2[nt], a0b, a1b, a2b, a3b, b0s, b1s);
                mma8(acc2[nt], a0s, a1s, a2s, a3s, b0b, b1b);
            }
        }
        __syncthreads();
    }

    // ---- epilogue: bias, optional tanh, * p, store ----
    const int bat = row0 / RPB;
    #pragma unroll
    for (int nt = 0; nt < NTB; nt++) {
        const int col = cw * (O / 8) + nt * 8 + tig * 2;
        float2 bv = *reinterpret_cast<const float2*>(bb + col);
        float2 pv = *reinterpret_cast<const float2*>(p + bat * O + col);
        const int rl = row0 + m0 + g;
        const int rh = rl + 8;
        float y0 = acc2[nt][0] + bv.x, y1 = acc2[nt][1] + bv.y;
        float y2 = acc2[nt][2] + bv.x, y3 = acc2[nt][3] + bv.y;
        if (!PLAIN) { y0 = ftanh(y0); y1 = ftanh(y1); y2 = ftanh(y2); y3 = ftanh(y3); }
        *reinterpret_cast<float2*>(outp + (size_t)rl * O + col) = make_float2(y0 * pv.x, y1 * pv.y);
        *reinterpret_cast<float2*>(outp + (size_t)rh * O + col) = make_float2(y2 * pv.x, y3 * pv.y);
    }
}

extern "C" void kernel_launch(void* const* d_in, const int* in_sizes, int n_in,
                              void* d_out, int out_size) {
    const float* par          = (const float*)d_in[0];
    const float* x            = (const float*)d_in[1];
    const float* pos          = (const float*)d_in[2];
    const float* x_skip_l1    = (const float*)d_in[4];
    const float* pos_skip_l1  = (const float*)d_in[5];
    const float* x_skip_l0    = (const float*)d_in[7];
    const float* pos_skip_l0  = (const float*)d_in[8];
    const int*   batch_skip_l0= (const int*)  d_in[9];
    const float* W0a = (const float*)d_in[10];
    const float* b0a = (const float*)d_in[11];
    const float* W0b = (const float*)d_in[12];
    const float* b0b = (const float*)d_in[13];
    const float* Wp0 = (const float*)d_in[14];
    const float* bp0 = (const float*)d_in[15];
    const float* W1a = (const float*)d_in[16];
    const float* b1a = (const float*)d_in[17];
    const float* W1b = (const float*)d_in[18];
    const float* b1b = (const float*)d_in[19];
    const float* Wp1 = (const float*)d_in[20];
    const float* bp1 = (const float*)d_in[21];
    float* out = (float*)d_out;

    const int smem1 = 32 * (KD1 + 4) * 4 + 2 * (H1 / 8) * 32 * 16;  // 49664+32768 = 82432
    const int smem2 = 32 * (KD2 + 4) * 4 + 2 * (H2 / 8) * 32 * 16;  // 25088+16384 = 41472
    cudaFuncSetAttribute(mlp_kernel<1>, cudaFuncAttributeMaxDynamicSharedMemorySize, smem1);
    cudaFuncSetAttribute(mlp_kernel<2>, cudaFuncAttributeMaxDynamicSharedMemorySize, smem2);

    const long long full = (long long)NT0 * O2 + (long long)NT0 * 3 + NT0;
    const int do_tail = ((long long)out_size >= full) ? 1 : 0;

    prep_kernel<<<(S1A + S1B + S2A + S2B + 255) / 256, 256>>>(
        W0a, W0b, W1a, W1b, par, Wp0, bp0, Wp1, bp1);

    knn_kernel<1><<<NT1 / 128, 512>>>(pos, pos_skip_l1);
    knn_kernel<2><<<NT0 / 128, 512>>>(pos_skip_l1, pos_skip_l0);

    mlp_kernel<1><<<NT1 / 32, 512, smem1>>>(b0a, b0b, x, x_skip_l1,
                                            nullptr, nullptr, 0, nullptr);
    mlp_kernel<2><<<NT0 / 32, 512, smem2>>>(b1a, b1b, nullptr, x_skip_l0,
                                            pos_skip_l0, batch_skip_l0, do_tail, out);
}

// round 16
// speedup vs baseline: 1.3082x; 1.3082x over previous
#include <cuda_runtime.h>
#include <cuda_bf16.h>
#include <cstdint>
#include <math.h>

// Problem constants
#define BATCH 4
#define MPAR  64
#define N2  512
#define N1  2048
#define N0  8192
#define C2  256
#define C1  128
#define C0  64

#define NT1 (BATCH * N1)          // 8192
#define NT0 (BATCH * N0)          // 32768
#define KD1 (C2 + C1)             // 384
#define H1  256
#define O1  128
#define KD2 (O1 + C0)             // 192
#define H2  128
#define O2  64

// packed bf16 fragment counts: (K/16) * (N/8) * 32 uint4 each
#define S1A ((KD1 / 16) * (H1 / 8) * 32)  // 24576
#define S1B ((H1 / 16) * (O1 / 8) * 32)   // 8192
#define S2A ((KD2 / 16) * (H2 / 8) * 32)  // 6144
#define S2B ((H2 / 16) * (O2 / 8) * 32)   // 2048

// -------- scratch (referenced ONLY from device code) --------
__device__ float  g_x1   [NT1 * O1];
__device__ int    g_idx1 [NT1 * 3];
__device__ float  g_w1   [NT1 * 3];
__device__ int    g_idx2 [NT0 * 3];
__device__ float  g_w2   [NT0 * 3];
__device__ float  g_p0   [BATCH * O1];
__device__ float  g_p1   [BATCH * O2];
// weights pre-packed into m16n8k16 bf16 B-fragment order:
// id = (k16step*(N/8) + ntile)*32 + lane; lane: g=lane>>2, tig=lane&3
// uint4 = { b0_big, b1_big, b0_small, b1_small }
//   b0 holds rows k0=16*step+2*tig, k0+1;  b1 holds rows k0+8, k0+9; col n=8*ntile+g
__device__ uint4 g_Wa1p[S1A];
__device__ uint4 g_Wb1p[S1B];
__device__ uint4 g_Wa2p[S2A];
__device__ uint4 g_Wb2p[S2B];

__device__ __forceinline__ float ftanh(float x) {
    float e = __expf(2.0f * x);
    return 1.0f - __fdividef(2.0f, e + 1.0f);
}

// pack two f32 into bf16x2 (element k -> low half, k+1 -> high half)
__device__ __forceinline__ uint32_t pk_bf2(float lo, float hi) {
    uint32_t u;
    asm("cvt.rn.bf16x2.f32 %0, %1, %2;" : "=r"(u) : "f"(hi), "f"(lo));
    return u;
}
__device__ __forceinline__ float bf_lo(uint32_t u) { return __uint_as_float(u << 16); }
__device__ __forceinline__ float bf_hi(uint32_t u) { return __uint_as_float(u & 0xFFFF0000u); }

__device__ __forceinline__ void mma16(float* c,
                                      uint32_t a0, uint32_t a1, uint32_t a2, uint32_t a3,
                                      uint32_t b0, uint32_t b1) {
    asm volatile(
        "mma.sync.aligned.m16n8k16.row.col.f32.bf16.bf16.f32 "
        "{%0,%1,%2,%3},{%4,%5,%6,%7},{%8,%9},{%0,%1,%2,%3};"
        : "+f"(c[0]), "+f"(c[1]), "+f"(c[2]), "+f"(c[3])
        : "r"(a0), "r"(a1), "r"(a2), "r"(a3), "r"(b0), "r"(b1));
}

// split one weight scalar: big = bf16(w), small = bf16(w - big)
__device__ __forceinline__ void pack_one(const float* __restrict__ W, int ncols, int ntf,
                                         int id, uint4* __restrict__ dst)
{
    int lane = id & 31;
    int rem  = id >> 5;
    int nt   = rem % ntf;
    int ks   = rem / ntf;
    int g = lane >> 2, tig = lane & 3;
    int n  = nt * 8 + g;
    int k0 = ks * 16 + 2 * tig;
    float w00 = W[(k0 + 0) * ncols + n], w01 = W[(k0 + 1) * ncols + n];
    float w10 = W[(k0 + 8) * ncols + n], w11 = W[(k0 + 9) * ncols + n];
    uint32_t B0 = pk_bf2(w00, w01);
    uint32_t B1 = pk_bf2(w10, w11);
    uint32_t S0 = pk_bf2(w00 - bf_lo(B0), w01 - bf_hi(B0));
    uint32_t S1 = pk_bf2(w10 - bf_lo(B1), w11 - bf_hi(B1));
    dst[id] = make_uint4(B0, B1, S0, S1);
}

// -------- prep: weight fragment packing + par branch (one launch) --------
__global__ void prep_kernel(const float* __restrict__ W0a, const float* __restrict__ W0b,
                            const float* __restrict__ W1a, const float* __restrict__ W1b,
                            const float* __restrict__ par,
                            const float* __restrict__ Wp0, const float* __restrict__ bp0,
                            const float* __restrict__ Wp1, const float* __restrict__ bp1)
{
    int i = blockIdx.x * 256 + threadIdx.x;
    if (i < S1A)                         pack_one(W0a, H1, H1 / 8, i, g_Wa1p);
    else if (i < S1A + S1B)              pack_one(W0b, O1, O1 / 8, i - S1A, g_Wb1p);
    else if (i < S1A + S1B + S2A)        pack_one(W1a, H2, H2 / 8, i - S1A - S1B, g_Wa2p);
    else if (i < S1A + S1B + S2A + S2B)  pack_one(W1b, O2, O2 / 8, i - S1A - S1B - S2A, g_Wb2p);

    if (blockIdx.x == 0 && threadIdx.x < 128) {
        int j = threadIdx.x;
        #pragma unroll
        for (int b = 0; b < BATCH; b++) {
            float a0 = 0.0f;
            #pragma unroll 8
            for (int m = 0; m < MPAR; m++)
                a0 = fmaf(par[b * MPAR + m], Wp0[m * O1 + j], a0);
            g_p0[b * O1 + j] = ftanh(a0 + bp0[j]);
            if (j < O2) {
                float a1 = 0.0f;
                #pragma unroll 8
                for (int m = 0; m < MPAR; m++)
                    a1 = fmaf(par[b * MPAR + m], Wp1[m * O2 + j], a1);
                g_p1[b * O2 + j] = ftanh(a1 + bp1[j]);
            }
        }
    }
}

// -------- KNN (k=3), 4-way source split, 4-wide min-screen --------
template<int LAYER>
__global__ __launch_bounds__(512) void knn_kernel(const float* __restrict__ pos_src,
                                                  const float* __restrict__ pos_tgt)
{
    constexpr int NS  = (LAYER == 1) ? N2 : N1;
    constexpr int TPB = (LAYER == 1) ? N1 : N0;
    constexpr int TPT = 128;
    constexpr int SC  = NS / 4;

    __shared__ float4 sp[NS];
    __shared__ float  sd[3][512];
    __shared__ int    si[3][512];

    int* __restrict__ idx_out  = (LAYER == 1) ? g_idx1 : g_idx2;
    float* __restrict__ w_out  = (LAYER == 1) ? g_w1   : g_w2;

    const int bpb = TPB / TPT;
    const int b   = blockIdx.x / bpb;
    const int t0  = (blockIdx.x % bpb) * TPT;
    const int tid = threadIdx.x;
    const int lt    = tid & (TPT - 1);
    const int chunk = tid >> 7;

    const float* ps = pos_src + (size_t)b * NS * 3;
    for (int i = tid; i < NS; i += 512) {
        float sx = ps[i * 3 + 0], sy = ps[i * 3 + 1], sz = ps[i * 3 + 2];
        sp[i] = make_float4(sx, sy, sz, fmaf(sx, sx, fmaf(sy, sy, sz * sz)));
    }
    __syncthreads();

    const int gt = b * TPB + t0 + lt;
    const float px = pos_tgt[gt * 3 + 0];
    const float py = pos_tgt[gt * 3 + 1];
    const float pz = pos_tgt[gt * 3 + 2];
    const float nx = -2.0f * px, ny = -2.0f * py, nz = -2.0f * pz;

    float d0 = 3.4e38f, d1 = 3.4e38f, d2 = 3.4e38f;
    int   i0 = 0, i1 = 0, i2 = 0;

    auto insert3 = [&](float d, int s) {
        if (d < d2) {
            if (d < d1) {
                d2 = d1; i2 = i1;
                if (d < d0) { d1 = d0; i1 = i0; d0 = d; i0 = s; }
                else        { d1 = d;  i1 = s; }
            } else { d2 = d; i2 = s; }
        }
    };

    const int sbeg = chunk * SC;
    #pragma unroll 2
    for (int s = sbeg; s < sbeg + SC; s += 4) {
        float4 va = sp[s + 0], vb = sp[s + 1], vc = sp[s + 2], vd = sp[s + 3];
        float da = fmaf(nx, va.x, fmaf(ny, va.y, fmaf(nz, va.z, va.w)));
        float db = fmaf(nx, vb.x, fmaf(ny, vb.y, fmaf(nz, vb.z, vb.w)));
        float dc = fmaf(nx, vc.x, fmaf(ny, vc.y, fmaf(nz, vc.z, vc.w)));
        float dd = fmaf(nx, vd.x, fmaf(ny, vd.y, fmaf(nz, vd.z, vd.w)));
        if (fminf(fminf(da, db), fminf(dc, dd)) < d2) {
            insert3(da, s);
            insert3(db, s + 1);
            insert3(dc, s + 2);
            insert3(dd, s + 3);
        }
    }

    sd[0][tid] = d0; sd[1][tid] = d1; sd[2][tid] = d2;
    si[0][tid] = i0; si[1][tid] = i1; si[2][tid] = i2;
    __syncthreads();

    if (tid < TPT) {
        #pragma unroll
        for (int c = 1; c < 4; c++) {
            #pragma unroll
            for (int j = 0; j < 3; j++)
                insert3(sd[j][c * TPT + lt], si[j][c * TPT + lt]);
        }

        float4 v0 = sp[i0], v1 = sp[i1], v2 = sp[i2];
        float dx, dy, dz;
        dx = px - v0.x; dy = py - v0.y; dz = pz - v0.z;
        float e0 = fmaf(dx, dx, fmaf(dy, dy, dz * dz));
        dx = px - v1.x; dy = py - v1.y; dz = pz - v1.z;
        float e1 = fmaf(dx, dx, fmaf(dy, dy, dz * dz));
        dx = px - v2.x; dy = py - v2.y; dz = pz - v2.z;
        float e2 = fmaf(dx, dx, fmaf(dy, dy, dz * dz));

        const int base = b * NS;
        idx_out[gt * 3 + 0] = base + i0;
        idx_out[gt * 3 + 1] = base + i1;
        idx_out[gt * 3 + 2] = base + i2;
        w_out[gt * 3 + 0] = __fdividef(1.0f, fmaxf(e0, 1e-16f));
        w_out[gt * 3 + 1] = __fdividef(1.0f, fmaxf(e1, 1e-16f));
        w_out[gt * 3 + 2] = __fdividef(1.0f, fmaxf(e2, 1e-16f));
    }
}

// -------- fused interp + concat + 2-layer MLP (split-bf16 m16n8k16) ----
// 256 threads / 8 warps: 2 row-warp groups (16 rows) x 4 col-warp groups.
// R = 32 rows. 3 bf16 MMAs per k16 n-tile: Ab*Bb + Ab*Bs + As*Bb.
template<int LAYER>
__global__ __launch_bounds__(256, 2) void mlp_kernel(
    const float* __restrict__ ba, const float* __restrict__ bb,
    const float* __restrict__ xsrc_arg, const float* __restrict__ xskip,
    const float* __restrict__ pos_tail, const int* __restrict__ bat_tail,
    int do_tail, float* __restrict__ out_arg)
{
    constexpr int KD  = (LAYER == 1) ? KD1 : KD2;   // 384 / 192
    constexpr int H   = (LAYER == 1) ? H1  : H2;    // 256 / 128
    constexpr int O   = (LAYER == 1) ? O1  : O2;    // 128 / 64
    constexpr int C   = (LAYER == 1) ? C2  : O1;    // interp width
    constexpr int CS  = KD - C;                     // skip width
    constexpr bool PLAIN = (LAYER == 2);
    constexpr int RPB = (LAYER == 1) ? N1 : N0;
    constexpr int XP  = KD + 4;                     // padded xs stride (floats)
    constexpr int HP  = H + 4;                      // padded hs stride (floats)
    constexpr int BK  = 32;                         // k per staged tile (2 k16 steps)
    constexpr int KT1 = KD / BK;                    // 12 / 6
    constexpr int KT2 = H / BK;                     // 8 / 4
    constexpr int NTF1 = H / 8;                     // fragment cols phase 1 (32/16)
    constexpr int NTF2 = O / 8;                     // fragment cols phase 2 (16/8)
    constexpr int NTA = NTF1 / 4;                   // n-tiles/warp phase1 (8/4)
    constexpr int NTB = NTF2 / 4;                   // n-tiles/warp phase2 (4/2)
    constexpr int PF1 = 2 * NTF1 * 32 / 256;        // uint4/thread per tile (8/4)
    constexpr int PF2 = 2 * NTF2 * 32 / 256;        // (4/2)

    extern __shared__ char smem_raw[];
    float* xs = (float*)smem_raw;                   // 32*XP floats; aliased as hs
    float* hs = xs;
    uint4* ws = (uint4*)(smem_raw + 32 * XP * 4);   // weight fragment tile

    const uint4* __restrict__ Wap = (LAYER == 1) ? g_Wa1p : g_Wa2p;
    const uint4* __restrict__ Wbp = (LAYER == 1) ? g_Wb1p : g_Wb2p;
    const float* __restrict__ xsrc = (LAYER == 1) ? xsrc_arg : g_x1;
    const int*   __restrict__ idx  = (LAYER == 1) ? g_idx1 : g_idx2;
    const float* __restrict__ wgt  = (LAYER == 1) ? g_w1   : g_w2;
    const float* __restrict__ p    = (LAYER == 1) ? g_p0 : g_p1;
    float*       __restrict__ outp = (LAYER == 1) ? g_x1 : out_arg;

    const int tid  = threadIdx.x;
    const int lane = tid & 31;
    const int w    = tid >> 5;           // 0..7
    const int rw   = w >> 2;             // 0..1 row-warp group
    const int cw   = w & 3;              // 0..3 col-warp group
    const int g    = lane >> 2;          // 0..7 mma group
    const int tig  = lane & 3;           // 0..3 thread-in-group
    const int m0   = rw * 16;
    const int row0 = blockIdx.x * 32;

    // ---- tail copy (LAYER 2 only) ----
    if (LAYER == 2 && do_tail && tid < 128) {
        const int i = blockIdx.x * 128 + tid;
        const int NP = NT0 * 3;
        float v = (i < NP) ? pos_tail[i] : (float)bat_tail[i - NP];
        out_arg[(size_t)NT0 * O2 + i] = v;
    }

    // ---- staging: interpolate + concat into xs (warp per row) ----
    for (int rr = w; rr < 32; rr += 8) {
        const int t = row0 + rr;
        const int j0 = idx[t * 3 + 0], j1 = idx[t * 3 + 1], j2 = idx[t * 3 + 2];
        float w0 = wgt[t * 3 + 0], w1 = wgt[t * 3 + 1], w2 = wgt[t * 3 + 2];
        const float inv = __fdividef(1.0f, w0 + w1 + w2);
        w0 *= inv; w1 *= inv; w2 *= inv;

        const float4* r0 = reinterpret_cast<const float4*>(xsrc + (size_t)j0 * C);
        const float4* r1 = reinterpret_cast<const float4*>(xsrc + (size_t)j1 * C);
        const float4* r2 = reinterpret_cast<const float4*>(xsrc + (size_t)j2 * C);
        float4* xrow4 = reinterpret_cast<float4*>(xs + rr * XP);

        #pragma unroll
        for (int c = lane; c < C / 4; c += 32) {
            float4 a = r0[c], bq = r1[c], cq = r2[c];
            float4 o;
            o.x = fmaf(w0, a.x, fmaf(w1, bq.x, w2 * cq.x));
            o.y = fmaf(w0, a.y, fmaf(w1, bq.y, w2 * cq.y));
            o.z = fmaf(w0, a.z, fmaf(w1, bq.z, w2 * cq.z));
            o.w = fmaf(w0, a.w, fmaf(w1, bq.w, w2 * cq.w));
            xrow4[c] = o;
        }
        const float4* sk = reinterpret_cast<const float4*>(xskip + (size_t)t * CS);
        #pragma unroll
        for (int c = lane; c < CS / 4; c += 32)
            xrow4[C / 4 + c] = sk[c];
    }

    // preload Wa tile 0 (packed fragments, linear)
    uint4 wr[PF1];
    #pragma unroll
    for (int j = 0; j < PF1; j++) wr[j] = Wap[j * 256 + tid];

    // ---- phase 1: X(32xKD) @ Wa(KDxH) -> tanh -> hs ----
    float acc[NTA][4];
    #pragma unroll
    for (int n = 0; n < NTA; n++)
        #pragma unroll
        for (int q = 0; q < 4; q++) acc[n][q] = 0.0f;

    for (int t = 0; t < KT1; t++) {
        #pragma unroll
        for (int j = 0; j < PF1; j++) ws[j * 256 + tid] = wr[j];
        __syncthreads();   // t==0 also orders xs staging before reads
        if (t + 1 < KT1) {
            #pragma unroll
            for (int j = 0; j < PF1; j++)
                wr[j] = Wap[(t + 1) * (PF1 * 256) + j * 256 + tid];
        }
        #pragma unroll
        for (int ks = 0; ks < 2; ks++) {
            const int kk = t * BK + ks * 16 + 2 * tig;
            float2 p0 = *reinterpret_cast<const float2*>(xs + (m0 + g) * XP + kk);
            float2 p1 = *reinterpret_cast<const float2*>(xs + (m0 + g + 8) * XP + kk);
            float2 p2 = *reinterpret_cast<const float2*>(xs + (m0 + g) * XP + kk + 8);
            float2 p3 = *reinterpret_cast<const float2*>(xs + (m0 + g + 8) * XP + kk + 8);
            uint32_t A0b = pk_bf2(p0.x, p0.y), A1b = pk_bf2(p1.x, p1.y);
            uint32_t A2b = pk_bf2(p2.x, p2.y), A3b = pk_bf2(p3.x, p3.y);
            uint32_t A0s = pk_bf2(p0.x - bf_lo(A0b), p0.y - bf_hi(A0b));
            uint32_t A1s = pk_bf2(p1.x - bf_lo(A1b), p1.y - bf_hi(A1b));
            uint32_t A2s = pk_bf2(p2.x - bf_lo(A2b), p2.y - bf_hi(A2b));
            uint32_t A3s = pk_bf2(p3.x - bf_lo(A3b), p3.y - bf_hi(A3b));
            #pragma unroll
            for (int nt = 0; nt < NTA; nt++) {
                uint4 f = ws[((2 * t + ks - 2 * t) * 0 + ks * NTF1 + cw * NTA + nt) * 32 + lane];
                mma16(acc[nt], A0b, A1b, A2b, A3b, f.x, f.y);
                mma16(acc[nt], A0b, A1b, A2b, A3b, f.z, f.w);
                mma16(acc[nt], A0s, A1s, A2s, A3s, f.x, f.y);
            }
        }
        __syncthreads();
    }

    // preload Wb tile 0
    uint4 wr2[PF2];
    #pragma unroll
    for (int j = 0; j < PF2; j++) wr2[j] = Wbp[j * 256 + tid];

    // tanh epilogue -> hs (aliases xs; all xs reads complete after final sync)
    #pragma unroll
    for (int nt = 0; nt < NTA; nt++) {
        const int col = cw * (H / 4) + nt * 8 + tig * 2;
        float2 bv = *reinterpret_cast<const float2*>(ba + col);
        float2 lo = make_float2(ftanh(acc[nt][0] + bv.x), ftanh(acc[nt][1] + bv.y));
        float2 hi = make_float2(ftanh(acc[nt][2] + bv.x), ftanh(acc[nt][3] + bv.y));
        *reinterpret_cast<float2*>(hs + (m0 + g) * HP + col)     = lo;
        *reinterpret_cast<float2*>(hs + (m0 + g + 8) * HP + col) = hi;
    }

    // ---- phase 2: hs(32xH) @ Wb(HxO) ----
    float acc2[NTB][4];
    #pragma unroll
    for (int n = 0; n < NTB; n++)
        #pragma unroll
        for (int q = 0; q < 4; q++) acc2[n][q] = 0.0f;

    for (int t = 0; t < KT2; t++) {
        #pragma unroll
        for (int j = 0; j < PF2; j++) ws[j * 256 + tid] = wr2[j];
        __syncthreads();   // t==0 also orders hs stores before hs reads
        if (t + 1 < KT2) {
            #pragma unroll
            for (int j = 0; j < PF2; j++)
                wr2[j] = Wbp[(t + 1) * (PF2 * 256) + j * 256 + tid];
        }
        #pragma unroll
        for (int ks = 0; ks < 2; ks++) {
            const int kk = t * BK + ks * 16 + 2 * tig;
            float2 p0 = *reinterpret_cast<const float2*>(hs + (m0 + g) * HP + kk);
            float2 p1 = *reinterpret_cast<const float2*>(hs + (m0 + g + 8) * HP + kk);
            float2 p2 = *reinterpret_cast<const float2*>(hs + (m0 + g) * HP + kk + 8);
            float2 p3 = *reinterpret_cast<const float2*>(hs + (m0 + g + 8) * HP + kk + 8);
            uint32_t A0b = pk_bf2(p0.x, p0.y), A1b = pk_bf2(p1.x, p1.y);
            uint32_t A2b = pk_bf2(p2.x, p2.y), A3b = pk_bf2(p3.x, p3.y);
            uint32_t A0s = pk_bf2(p0.x - bf_lo(A0b), p0.y - bf_hi(A0b));
            uint32_t A1s = pk_bf2(p1.x - bf_lo(A1b), p1.y - bf_hi(A1b));
            uint32_t A2s = pk_bf2(p2.x - bf_lo(A2b), p2.y - bf_hi(A2b));
            uint32_t A3s = pk_bf2(p3.x - bf_lo(A3b), p3.y - bf_hi(A3b));
            #pragma unroll
            for (int nt = 0; nt < NTB; nt++) {
                uint4 f = ws[(ks * NTF2 + cw * NTB + nt) * 32 + lane];
                mma16(acc2[nt], A0b, A1b, A2b, A3b, f.x, f.y);
                mma16(acc2[nt], A0b, A1b, A2b, A3b, f.z, f.w);
                mma16(acc2[nt], A0s, A1s, A2s, A3s, f.x, f.y);
            }
        }
        __syncthreads();
    }

    // ---- epilogue: bias, optional tanh, * p, store ----
    const int bat = row0 / RPB;
    #pragma unroll
    for (int nt = 0; nt < NTB; nt++) {
        const int col = cw * (O / 4) + nt * 8 + tig * 2;
        float2 bv = *reinterpret_cast<const float2*>(bb + col);
        float2 pv = *reinterpret_cast<const float2*>(p + bat * O + col);
        const int rl = row0 + m0 + g;
        const int rh = rl + 8;
        float y0 = acc2[nt][0] + bv.x, y1 = acc2[nt][1] + bv.y;
        float y2 = acc2[nt][2] + bv.x, y3 = acc2[nt][3] + bv.y;
        if (!PLAIN) { y0 = ftanh(y0); y1 = ftanh(y1); y2 = ftanh(y2); y3 = ftanh(y3); }
        *reinterpret_cast<float2*>(outp + (size_t)rl * O + col) = make_float2(y0 * pv.x, y1 * pv.y);
        *reinterpret_cast<float2*>(outp + (size_t)rh * O + col) = make_float2(y2 * pv.x, y3 * pv.y);
    }
}

extern "C" void kernel_launch(void* const* d_in, const int* in_sizes, int n_in,
                              void* d_out, int out_size) {
    const float* par          = (const float*)d_in[0];
    const float* x            = (const float*)d_in[1];
    const float* pos          = (const float*)d_in[2];
    const float* x_skip_l1    = (const float*)d_in[4];
    const float* pos_skip_l1  = (const float*)d_in[5];
    const float* x_skip_l0    = (const float*)d_in[7];
    const float* pos_skip_l0  = (const float*)d_in[8];
    const int*   batch_skip_l0= (const int*)  d_in[9];
    const float* W0a = (const float*)d_in[10];
    const float* b0a = (const float*)d_in[11];
    const float* W0b = (const float*)d_in[12];
    const float* b0b = (const float*)d_in[13];
    const float* Wp0 = (const float*)d_in[14];
    const float* bp0 = (const float*)d_in[15];
    const float* W1a = (const float*)d_in[16];
    const float* b1a = (const float*)d_in[17];
    const float* W1b = (const float*)d_in[18];
    const float* b1b = (const float*)d_in[19];
    const float* Wp1 = (const float*)d_in[20];
    const float* bp1 = (const float*)d_in[21];
    float* out = (float*)d_out;

    // xs + 1 weight fragment tile (2 k16-steps)
    const int smem1 = 32 * (KD1 + 4) * 4 + 2 * (H1 / 8) * 32 * 16;  // 49664+32768 = 82432
    const int smem2 = 32 * (KD2 + 4) * 4 + 2 * (H2 / 8) * 32 * 16;  // 25088+16384 = 41472
    cudaFuncSetAttribute(mlp_kernel<1>, cudaFuncAttributeMaxDynamicSharedMemorySize, smem1);
    cudaFuncSetAttribute(mlp_kernel<2>, cudaFuncAttributeMaxDynamicSharedMemorySize, smem2);

    const long long full = (long long)NT0 * O2 + (long long)NT0 * 3 + NT0;
    const int do_tail = ((long long)out_size >= full) ? 1 : 0;

    prep_kernel<<<(S1A + S1B + S2A + S2B + 255) / 256, 256>>>(
        W0a, W0b, W1a, W1b, par, Wp0, bp0, Wp1, bp1);

    knn_kernel<1><<<NT1 / 128, 512>>>(pos, pos_skip_l1);
    knn_kernel<2><<<NT0 / 128, 512>>>(pos_skip_l1, pos_skip_l0);

    mlp_kernel<1><<<NT1 / 32, 256, smem1>>>(b0a, b0b, x, x_skip_l1,
                                            nullptr, nullptr, 0, nullptr);
    mlp_kernel<2><<<NT0 / 32, 256, smem2>>>(b1a, b1b, nullptr, x_skip_l0,
                                            pos_skip_l0, batch_skip_l0, do_tail, out);
}